// round 12
// baseline (speedup 1.0000x reference)
#include <cuda_runtime.h>

#define SZ   256          // image size
#define NT   256          // number of triangles
#define QSTRIDE 5         // float4 per triangle record (80B: kills bank conflicts)

// Per-triangle record layout (float4 index, stride 5, 80 B):
//  q0 : pAB edge: ax(=v1x), ay(=v1y), dy(=v0y-v1y), dx(=v0x-v1x)
//  q1 : pCB edge: ax(=v2x), ay(=v2y), dy(=v1y-v2y), dx(=v1x-v2x)
//  q2 : pCA edge: ax(=v0x), ay(=v0y), dy(=v2y-v0y), dx(=v2x-v0x)
//  q3 : invw, z0, z1, z2
//  q4 : pad (written zero)
// Slot NT is an all-zero "null" record: prod==0 -> never taken. Used to pad
// the candidate list so the dual-accumulator loop needs no tail guard.
//
// UV data is NOT staged: the winning triangle's uvs are fetched from global
// in the tail (once per pixel) and transformed there — identical arithmetic.
//
// Block: 256 threads = 64 pixels (8x8 tile) x 4 triangle slices.
// Warp layout: lane = slice*8 + pixCol, warp index = pixRow within tile.
// Grid: (32, 32) = 1024 blocks at 6 CTAs/SM (best measured config, R6).
//
// The z-buffer scan reduces to an argmax over covering triangles with ties
// broken by larger triangle index ('inside' => all barycentric weights > 0 =>
// z is a convex combination of vertex z's => z >= global zmin, so the zbuf
// init never matters for covered pixels). Argmax is order-independent AND
// associative over (z, off) lexicographic max: the candidate list needs no
// ordering, slices merge by shuffle, and each slice may keep TWO independent
// accumulators (even/odd list slots) combined after the loop — this breaks
// the serial select-chain dependency that capped issue at ~55%.
//
// Edge culling: each edge function e(p) is affine in p, so over the tile
// rectangle its max is at a corner. If any edge's corner-max <= -1e-5
// (rounding of O(1) fp32 values is < 1e-6), no pixel in the tile can have
// all three edge values strictly positive -> triangle cannot win any pixel.
//
// NOTE: the inside-test arithmetic form (px-ax)*dy-(py-ay)*dx must match the
// reference exactly — refactoring it flips boundary pixels and fails 1e-3.
__global__ __launch_bounds__(256, 6)
void render_kernel(const float* __restrict__ tris,
                   const float* __restrict__ uvs,
                   const float* __restrict__ uvmap,
                   float* __restrict__ out) {
    __shared__ __align__(16) float4 s_q[(NT + 1) * QSTRIDE];  // ~20.6 KB
    __shared__ unsigned short s_list[NT + 8];                 // quad offsets (tt*5)
    __shared__ int s_cnt;

    int tid   = threadIdx.x;
    int lane  = tid & 31;
    int warp  = tid >> 5;
    int slice = lane >> 3;        // 0..3
    int pcol  = lane & 7;         // 0..7

    const float d = 2.0f / 255.0f;

    if (tid == 0) s_cnt = 0;
    if (tid < QSTRIDE)            // null record (never wins: prod == 0)
        s_q[NT * QSTRIDE + tid] = make_float4(0.0f, 0.0f, 0.0f, 0.0f);

    // Tile corner coordinates, computed with the exact per-pixel formula.
    int jx0 = blockIdx.x * 8, jx1 = jx0 + 7;
    int iy0 = blockIdx.y * 8, iy1 = iy0 + 7;
    float cx0 = -1.0f + (float)jx0 * d;   // px at pcol=0
    float cx1 = -1.0f + (float)jx1 * d;   // px at pcol=7
    float cy0 =  1.0f - (float)iy0 * d;   // py at row=0 (max y)
    float cy1 =  1.0f - (float)iy1 * d;   // py at row=7 (min y)

    // ---- Fused prep: thread t builds triangle t's record in shared ----
    bool keep;
    {
        const float* T = tris + tid * 9;
        float v0x = __ldg(T + 0), v0y = __ldg(T + 1), v0z = __ldg(T + 2);
        float v1x = __ldg(T + 3), v1y = __ldg(T + 4), v1z = __ldg(T + 5);
        float v2x = __ldg(T + 6), v2y = __ldg(T + 7), v2z = __ldg(T + 8);

        float w = (v1x - v0x) * (v2y - v0y) - (v1y - v0y) * (v2x - v0x);
        bool valid = (w >= 1e-9f);
        float ws = valid ? w : 1.0f;
        float invw = 1.0f / ws;

        float4* Q = s_q + tid * QSTRIDE;
        Q[0] = make_float4(v1x, v1y, v0y - v1y, v0x - v1x);
        Q[1] = make_float4(v2x, v2y, v1y - v2y, v1x - v2x);
        Q[2] = make_float4(v0x, v0y, v2y - v0y, v2x - v0x);
        Q[3] = make_float4(invw, v0z, v1z, v2z);
        Q[4] = make_float4(0.0f, 0.0f, 0.0f, 0.0f);

        // Edge corner-max cull: e = (cx-ax)*dy - (cy-ay)*dx is separable,
        // max = max_x[(cx-ax)*dy] + max_y[-(cy-ay)*dx].
        #define EDGE_MAX(ax, ay, dy, dx) \
            (fmaxf((cx0 - (ax)) * (dy), (cx1 - (ax)) * (dy)) + \
             fmaxf(-((cy0 - (ay)) * (dx)), -((cy1 - (ay)) * (dx))))
        float mAB = EDGE_MAX(v1x, v1y, v0y - v1y, v0x - v1x);
        float mCB = EDGE_MAX(v2x, v2y, v1y - v2y, v1x - v2x);
        float mCA = EDGE_MAX(v0x, v0y, v2y - v0y, v2x - v0x);
        #undef EDGE_MAX

        keep = valid && (mAB > -1e-5f) && (mCB > -1e-5f) && (mCA > -1e-5f);
    }

    // Unordered compaction: ballot + one shared atomic per warp.
    __syncthreads();
    unsigned mask = __ballot_sync(0xffffffffu, keep);
    int base = 0;
    if (lane == 0 && mask) base = atomicAdd(&s_cnt, __popc(mask));
    base = __shfl_sync(0xffffffffu, base, 0);
    if (keep)
        s_list[base + __popc(mask & ((1u << lane) - 1u))] =
            (unsigned short)(tid * QSTRIDE);   // quad offset; monotone in tid
    __syncthreads();
    int cnt = s_cnt;
    if (tid < 8) s_list[cnt + tid] = (unsigned short)(NT * QSTRIDE); // null pad
    __syncthreads();

    // Pixel coordinates: pts[i][j] = (lin[j], lin[255-i]), lin[k] = -1 + k*2/255
    int j = jx0 + pcol;
    int i = iy0 + warp;
    float px = -1.0f + (float)j * d;
    float py =  1.0f - (float)i * d;

    // Dual independent accumulators per slice (slots k and k+4): the two
    // select chains have NO cross-dependency inside the loop, doubling ILP.
    float zb0 = -3.402823466e+38f, w10 = 0.0f, w20 = 0.0f; int bi0 = -1;
    float zb1 = -3.402823466e+38f, w11 = 0.0f, w21 = 0.0f; int bi1 = -1;

    #define EVAL(OFF, ZB, BI, W1S, W2S)                                      \
    {                                                                        \
        int off = (OFF);                                                     \
        float4 q0 = s_q[off], q1 = s_q[off + 1],                             \
               q2 = s_q[off + 2], q3 = s_q[off + 3];                         \
        float pAB = (px - q0.x) * q0.z - (py - q0.y) * q0.w;                 \
        float pCB = (px - q1.x) * q1.z - (py - q1.y) * q1.w;                 \
        float pCA = (px - q2.x) * q2.z - (py - q2.y) * q2.w;                 \
        float prod = fmaxf(pAB, 0.0f) * fmaxf(pCB, 0.0f) * fmaxf(pCA, 0.0f); \
        float w1 = pCB * q3.x;                                               \
        float w2 = pCA * q3.x;                                               \
        float w3 = 1.0f - w1 - w2;                                           \
        float z  = w1 * q3.y + w2 * q3.z + w3 * q3.w;                        \
        bool take = (prod > 0.0f) &&                                         \
                    ((z > (ZB)) || ((z == (ZB)) && (off > (BI))));           \
        ZB  = take ? z   : ZB;                                               \
        BI  = take ? off : BI;                                               \
        W1S = take ? w1  : W1S;                                              \
        W2S = take ? w2  : W2S;                                              \
    }

    for (int k = slice; k < cnt; k += 8) {
        int offA = s_list[k];
        int offB = s_list[k + 4];
        EVAL(offA, zb0, bi0, w10, w20);
        EVAL(offB, zb1, bi1, w11, w21);
    }
    #undef EVAL

    // Combine the two accumulators (associative lexicographic max).
    float zb = zb0, w1s = w10, w2s = w20; int bi = bi0;
    {
        bool take = (zb1 > zb) || ((zb1 == zb) && (bi1 > bi));
        if (take) { zb = zb1; bi = bi1; w1s = w11; w2s = w21; }
    }

    // Merge the 4 slices of each pixel: (z, off) max, ties -> larger off.
    #pragma unroll
    for (int off = 8; off < 32; off <<= 1) {
        float oz = __shfl_down_sync(0xffffffffu, zb, off);
        int   oi = __shfl_down_sync(0xffffffffu, bi, off);
        float o1 = __shfl_down_sync(0xffffffffu, w1s, off);
        float o2 = __shfl_down_sync(0xffffffffu, w2s, off);
        bool take = (oz > zb) || ((oz == zb) && (oi > bi));
        if (take) { zb = oz; bi = oi; w1s = o1; w2s = o2; }
    }

    // Deferred UV interpolation + bilinear texture sample (winner only),
    // computed in slice-0 lanes; then a warp transpose so the 32 output
    // values (4 channels x 8 pixels) store as 4 coalesced 32B segments.
    float r = 0.0f, g = 0.0f, b = 0.0f, a = 0.0f;
    if (slice == 0 && bi >= 0) {
        a = 1.0f;
        const float* U = uvs + (bi / QSTRIDE) * 6;   // bi = tt*QSTRIDE
        float u0 = __ldg(U + 0) * 2.0f - 1.0f, v0 = __ldg(U + 1) * 2.0f - 1.0f;
        float u1 = __ldg(U + 2) * 2.0f - 1.0f, v1 = __ldg(U + 3) * 2.0f - 1.0f;
        float u2 = __ldg(U + 4) * 2.0f - 1.0f, v2 = __ldg(U + 5) * 2.0f - 1.0f;
        float w3 = 1.0f - w1s - w2s;
        float uu = w1s * u0 + w2s * u1 + w3 * u2;
        float vv = w1s * v0 + w2s * v1 + w3 * v2;

        float x = (uu + 1.0f) * 0.5f * 1023.0f;
        float y = (vv + 1.0f) * 0.5f * 1023.0f;
        float x0f = floorf(x);
        float y0f = floorf(y);
        float wx = x - x0f;
        float wy = y - y0f;
        #pragma unroll
        for (int cy = 0; cy < 2; cy++) {
            #pragma unroll
            for (int cx = 0; cx < 2; cx++) {
                float ix = x0f + (float)cx;
                float iy = y0f + (float)cy;
                bool inb = (ix >= 0.0f) && (ix <= 1023.0f) &&
                           (iy >= 0.0f) && (iy <= 1023.0f);
                if (inb) {
                    int ii = (int)ix;
                    int jj = (int)iy;
                    float wgt = (cx ? wx : 1.0f - wx) * (cy ? wy : 1.0f - wy);
                    int toff = jj * 1024 + ii;
                    r += __ldg(uvmap + toff) * wgt;
                    g += __ldg(uvmap + 1048576 + toff) * wgt;
                    b += __ldg(uvmap + 2097152 + toff) * wgt;
                }
            }
        }
    }

    // Warp transpose: lane l stores channel (l>>3) of pixel (l&7).
    {
        int p = lane & 7;        // source pixel (slice-0 lane)
        int c = lane >> 3;       // channel
        float vr = __shfl_sync(0xffffffffu, r, p);
        float vg = __shfl_sync(0xffffffffu, g, p);
        float vb = __shfl_sync(0xffffffffu, b, p);
        float va = __shfl_sync(0xffffffffu, a, p);
        float v  = (c == 0) ? vr : (c == 1) ? vg : (c == 2) ? vb : va;
        out[c * 65536 + i * SZ + jx0 + p] = v;
    }
}

extern "C" void kernel_launch(void* const* d_in, const int* in_sizes, int n_in,
                              void* d_out, int out_size) {
    const float* tris  = (const float*)d_in[0];   // (256,3,3)
    const float* uvs   = (const float*)d_in[1];   // (256,3,2)
    const float* uvmap = (const float*)d_in[2];   // (3,1024,1024)
    float* out = (float*)d_out;                   // (4,256,256)

    dim3 block(256);
    dim3 grid(SZ / 8, SZ / 8);
    render_kernel<<<grid, block>>>(tris, uvs, uvmap, out);
}

// round 13
// speedup vs baseline: 1.0507x; 1.0507x over previous
#include <cuda_runtime.h>

#define SZ   256          // image size
#define NT   256          // number of triangles
#define QSTRIDE 5         // float4 per record slot (80B: bank-conflict-free)

// COMPACTED per-tile record table: slot k holds the k-th surviving triangle.
//  q0 : pAB edge: ax(=v1x), ay(=v1y), dy(=v0y-v1y), dx(=v0x-v1x)
//  q1 : pCB edge: ax(=v2x), ay(=v2y), dy(=v1y-v2y), dx(=v1x-v2x)
//  q2 : pCA edge: ax(=v0x), ay(=v0y), dy(=v2y-v0y), dx(=v2x-v0x)
//  q3 : invw, z0, z1, z2
//  (q4 pad never written — stride only exists for bank spreading)
// s_idx[k] = original triangle index (for tie-break + UV fetch).
// Slots cnt..cnt+7 are zeroed null records: prod==0 -> never taken, so the
// x2-unrolled loop needs no tail guard.
//
// Only surviving triangles write records: STS traffic per block drops ~8x vs
// writing all 256, and the inner loop needs NO list indirection — record
// addresses are pure induction variables (the old LDS.U16 -> IMAD -> LDS.128
// serial chain is gone; s_idx is read only for the select, off-path).
//
// Block: 256 threads = 64 pixels (8x8 tile) x 4 triangle slices.
// Warp layout: lane = slice*8 + pixCol, warp index = pixRow within tile.
// Grid: (32, 32) = 1024 blocks at 6 CTAs/SM (best measured config).
// Within a warp the 4 slices read consecutive slots (80B apart): LDS.128
// addresses land in disjoint bank groups -> conflict-free.
//
// The z-buffer scan reduces to an argmax over covering triangles with ties
// broken by larger triangle index ('inside' => all barycentric weights > 0 =>
// z >= global zmin, a convex combination of vertex z's, so the zbuf init
// never matters for covered pixels). Argmax is order-independent: compaction
// order is irrelevant because the tie-break compares original indices.
//
// Edge culling: each edge function e(p) is affine in p, so over the tile
// rectangle its max is at a corner. If any edge's corner-max <= -1e-5
// (rounding of O(1) fp32 values is < 1e-6), no pixel in the tile can have
// all three edge values strictly positive -> triangle cannot win any pixel.
//
// NOTE: the inside-test arithmetic form (px-ax)*dy-(py-ay)*dx must match the
// reference exactly — refactoring it flips boundary pixels and fails 1e-3.
__global__ __launch_bounds__(256, 6)
void render_kernel(const float* __restrict__ tris,
                   const float* __restrict__ uvs,
                   const float* __restrict__ uvmap,
                   float* __restrict__ out) {
    __shared__ __align__(16) float4 s_q[(NT + 8) * QSTRIDE];  // ~20.6 KB
    __shared__ short s_idx[NT + 8];
    __shared__ int s_cnt;

    int tid   = threadIdx.x;
    int lane  = tid & 31;
    int warp  = tid >> 5;
    int slice = lane >> 3;        // 0..3
    int pcol  = lane & 7;         // 0..7

    const float d = 2.0f / 255.0f;

    if (tid == 0) s_cnt = 0;

    // Tile corner coordinates, computed with the exact per-pixel formula.
    int jx0 = blockIdx.x * 8, jx1 = jx0 + 7;
    int iy0 = blockIdx.y * 8, iy1 = iy0 + 7;
    float cx0 = -1.0f + (float)jx0 * d;   // px at pcol=0
    float cx1 = -1.0f + (float)jx1 * d;   // px at pcol=7
    float cy0 =  1.0f - (float)iy0 * d;   // py at row=0 (max y)
    float cy1 =  1.0f - (float)iy1 * d;   // py at row=7 (min y)

    // ---- Prep: thread t culls triangle t; survivors write records
    //      directly into their COMPACTED slot.
    {
        const float* T = tris + tid * 9;
        float v0x = __ldg(T + 0), v0y = __ldg(T + 1), v0z = __ldg(T + 2);
        float v1x = __ldg(T + 3), v1y = __ldg(T + 4), v1z = __ldg(T + 5);
        float v2x = __ldg(T + 6), v2y = __ldg(T + 7), v2z = __ldg(T + 8);

        float w = (v1x - v0x) * (v2y - v0y) - (v1y - v0y) * (v2x - v0x);
        bool valid = (w >= 1e-9f);

        // Edge corner-max cull: e = (cx-ax)*dy - (cy-ay)*dx is separable,
        // max = max_x[(cx-ax)*dy] + max_y[-(cy-ay)*dx].
        #define EDGE_MAX(ax, ay, dy, dx) \
            (fmaxf((cx0 - (ax)) * (dy), (cx1 - (ax)) * (dy)) + \
             fmaxf(-((cy0 - (ay)) * (dx)), -((cy1 - (ay)) * (dx))))
        float mAB = EDGE_MAX(v1x, v1y, v0y - v1y, v0x - v1x);
        float mCB = EDGE_MAX(v2x, v2y, v1y - v2y, v1x - v2x);
        float mCA = EDGE_MAX(v0x, v0y, v2y - v0y, v2x - v0x);
        #undef EDGE_MAX

        bool keep = valid && (mAB > -1e-5f) && (mCB > -1e-5f) && (mCA > -1e-5f);

        // Warp-level compaction: one shared atomic per warp.
        // (s_cnt was zeroed before this sync point via the barrier below? No:
        //  s_cnt=0 happens before any atomics because all atomics come after
        //  this ballot, and tid==0 wrote it before any __syncthreads. To be
        //  safe we order with a syncthreads here — prep above hides it.)
        unsigned mask = __ballot_sync(0xffffffffu, keep);
        __syncthreads();   // orders s_cnt=0 before atomics (and smem reuse)
        int base = 0;
        if (lane == 0 && mask) base = atomicAdd(&s_cnt, __popc(mask));
        base = __shfl_sync(0xffffffffu, base, 0);

        if (keep) {
            int slot = base + __popc(mask & ((1u << lane) - 1u));
            float ws = valid ? w : 1.0f;     // valid==true here
            float invw = 1.0f / ws;
            float4* Q = s_q + slot * QSTRIDE;
            Q[0] = make_float4(v1x, v1y, v0y - v1y, v0x - v1x);
            Q[1] = make_float4(v2x, v2y, v1y - v2y, v1x - v2x);
            Q[2] = make_float4(v0x, v0y, v2y - v0y, v2x - v0x);
            Q[3] = make_float4(invw, v0z, v1z, v2z);
            s_idx[slot] = (short)tid;
        }
    }
    __syncthreads();
    int cnt = s_cnt;
    if (tid < 8) {                 // null-pad slots cnt..cnt+7
        float4* Q = s_q + (cnt + tid) * QSTRIDE;
        float4 z4 = make_float4(0.0f, 0.0f, 0.0f, 0.0f);
        Q[0] = z4; Q[1] = z4; Q[2] = z4; Q[3] = z4;
        s_idx[cnt + tid] = -1;
    }
    __syncthreads();

    // Pixel coordinates: pts[i][j] = (lin[j], lin[255-i]), lin[k] = -1 + k*2/255
    int j = jx0 + pcol;
    int i = iy0 + warp;
    float px = -1.0f + (float)j * d;
    float py =  1.0f - (float)i * d;

    // Each slice scans every 4th slot, two per loop iteration (second may be
    // a null record -> never taken). Record addresses are induction variables;
    // s_idx is only consumed by the select. Tie-break: larger original index.
    float zb  = -3.402823466e+38f;
    float w1s = 0.0f, w2s = 0.0f;
    int   bidx = -1;

    #define EVAL(SLOT)                                                       \
    {                                                                        \
        const float4* Q = s_q + (SLOT) * QSTRIDE;                            \
        int idx = s_idx[SLOT];                                               \
        float4 q0 = Q[0], q1 = Q[1], q2 = Q[2], q3 = Q[3];                   \
        float pAB = (px - q0.x) * q0.z - (py - q0.y) * q0.w;                 \
        float pCB = (px - q1.x) * q1.z - (py - q1.y) * q1.w;                 \
        float pCA = (px - q2.x) * q2.z - (py - q2.y) * q2.w;                 \
        float prod = fmaxf(pAB, 0.0f) * fmaxf(pCB, 0.0f) * fmaxf(pCA, 0.0f); \
        float w1 = pCB * q3.x;                                               \
        float w2 = pCA * q3.x;                                               \
        float w3 = 1.0f - w1 - w2;                                           \
        float z  = w1 * q3.y + w2 * q3.z + w3 * q3.w;                        \
        bool take = (prod > 0.0f) &&                                         \
                    ((z > zb) || ((z == zb) && (idx > bidx)));               \
        zb   = take ? z   : zb;                                              \
        bidx = take ? idx : bidx;                                            \
        w1s  = take ? w1  : w1s;                                             \
        w2s  = take ? w2  : w2s;                                             \
    }

    for (int k = slice; k < cnt; k += 8) {
        EVAL(k);
        EVAL(k + 4);
    }
    #undef EVAL

    // Merge the 4 slices of each pixel: (z, idx) max, ties -> larger idx.
    #pragma unroll
    for (int off = 8; off < 32; off <<= 1) {
        float oz = __shfl_down_sync(0xffffffffu, zb, off);
        int   oi = __shfl_down_sync(0xffffffffu, bidx, off);
        float o1 = __shfl_down_sync(0xffffffffu, w1s, off);
        float o2 = __shfl_down_sync(0xffffffffu, w2s, off);
        bool take = (oz > zb) || ((oz == zb) && (oi > bidx));
        if (take) { zb = oz; bidx = oi; w1s = o1; w2s = o2; }
    }

    if (slice == 0) {
        // Deferred UV interpolation + bilinear texture sample (winner only)
        float r = 0.0f, g = 0.0f, b = 0.0f, a = 0.0f;
        if (bidx >= 0) {
            a = 1.0f;
            const float* U = uvs + bidx * 6;
            float u0 = __ldg(U + 0) * 2.0f - 1.0f, v0 = __ldg(U + 1) * 2.0f - 1.0f;
            float u1 = __ldg(U + 2) * 2.0f - 1.0f, v1 = __ldg(U + 3) * 2.0f - 1.0f;
            float u2 = __ldg(U + 4) * 2.0f - 1.0f, v2 = __ldg(U + 5) * 2.0f - 1.0f;
            float w3 = 1.0f - w1s - w2s;
            float uu = w1s * u0 + w2s * u1 + w3 * u2;
            float vv = w1s * v0 + w2s * v1 + w3 * v2;

            float x = (uu + 1.0f) * 0.5f * 1023.0f;
            float y = (vv + 1.0f) * 0.5f * 1023.0f;
            float x0f = floorf(x);
            float y0f = floorf(y);
            float wx = x - x0f;
            float wy = y - y0f;
            #pragma unroll
            for (int cy = 0; cy < 2; cy++) {
                #pragma unroll
                for (int cx = 0; cx < 2; cx++) {
                    float ix = x0f + (float)cx;
                    float iy = y0f + (float)cy;
                    bool inb = (ix >= 0.0f) && (ix <= 1023.0f) &&
                               (iy >= 0.0f) && (iy <= 1023.0f);
                    if (inb) {
                        int ii = (int)ix;
                        int jj = (int)iy;
                        float wgt = (cx ? wx : 1.0f - wx) * (cy ? wy : 1.0f - wy);
                        int toff = jj * 1024 + ii;
                        r += __ldg(uvmap + toff) * wgt;
                        g += __ldg(uvmap + 1048576 + toff) * wgt;
                        b += __ldg(uvmap + 2097152 + toff) * wgt;
                    }
                }
            }
        }

        int pix = i * SZ + j;
        out[pix]              = r;
        out[65536 + pix]      = g;
        out[2 * 65536 + pix]  = b;
        out[3 * 65536 + pix]  = a;
    }
}

extern "C" void kernel_launch(void* const* d_in, const int* in_sizes, int n_in,
                              void* d_out, int out_size) {
    const float* tris  = (const float*)d_in[0];   // (256,3,3)
    const float* uvs   = (const float*)d_in[1];   // (256,3,2)
    const float* uvmap = (const float*)d_in[2];   // (3,1024,1024)
    float* out = (float*)d_out;                   // (4,256,256)

    dim3 block(256);
    dim3 grid(SZ / 8, SZ / 8);
    render_kernel<<<grid, block>>>(tris, uvs, uvmap, out);
}